// round 4
// baseline (speedup 1.0000x reference)
#include <cuda_runtime.h>
#include <cstdint>

// ParabolicPool2D: out[b,c,oh,ow] = max_{p,q in 0..2} f[b,c,2*oh+p,2*ow+q] + h[c,p,q]
// h[c,p,q] = -((zp^2+zq^2)/2) * t[c],  z = {-1,0,1}
//          = a[p] + a[q]  with a[0]=a[2]=-t[c]/2, a[1]=0   (separable!)
//
// => rowred[r,ow] = max( max(f[r,2ow], f[r,2ow+2]) + a, f[r,2ow+1] )
//    out[oh,ow]   = max( max(rowred[2oh], rowred[2oh+2]) + a, rowred[2oh+1] )

#define B_  16
#define C_  128
#define H_  256
#define W_  256
#define OH_ 127
#define OW_ 127
#define SEGS 4
#define SEG_ROWS 32   // oh rows per segment (last segment has 31)

__global__ __launch_bounds__(64, 16)
void parabolic_pool_kernel(const float* __restrict__ f,
                           const float* __restrict__ t,
                           float* __restrict__ out)
{
    const int tx    = threadIdx.x;        // 0..63, owns output cols 2*tx and 2*tx+1
    const int plane = blockIdx.x;         // b*C + c
    const int seg   = blockIdx.y;         // oh segment

    const int c = plane & (C_ - 1);
    const float a = -0.5f * __ldg(&t[c]);

    const float* fp = f + (size_t)plane * (H_ * W_);
    float*       op = out + (size_t)plane * (OH_ * OW_);

    const int col  = tx * 4;              // input column base (16B aligned)
    const bool has2 = (tx < 63);          // second output column valid (ow1 <= 126)

    const int oh0 = seg * SEG_ROWS;
    const int nh  = min(SEG_ROWS, OH_ - oh0);

    // ---- prime: row-reduce input row r0 = 2*oh0 ----
    const float* row = fp + (2 * oh0) * W_ + col;
    float4 v  = *reinterpret_cast<const float4*>(row);
    float  v4 = has2 ? row[4] : 0.0f;

    float ra0 = fmaxf(fmaxf(v.x, v.z) + a, v.y);
    float ra1 = fmaxf(fmaxf(v.z, v4)  + a, v.w);

    float* orow = op + oh0 * OW_ + 2 * tx;

    #pragma unroll 2
    for (int i = 0; i < nh; ++i) {
        // two new input rows per output row
        const float* rb = row + W_;
        const float* rc = row + 2 * W_;
        float4 vb  = *reinterpret_cast<const float4*>(rb);
        float4 vc  = *reinterpret_cast<const float4*>(rc);
        float  vb4 = has2 ? rb[4] : 0.0f;
        float  vc4 = has2 ? rc[4] : 0.0f;
        row = rc;

        float rb0 = fmaxf(fmaxf(vb.x, vb.z) + a, vb.y);
        float rb1 = fmaxf(fmaxf(vb.z, vb4)  + a, vb.w);
        float rc0 = fmaxf(fmaxf(vc.x, vc.z) + a, vc.y);
        float rc1 = fmaxf(fmaxf(vc.z, vc4)  + a, vc.w);

        float o0 = fmaxf(fmaxf(ra0, rc0) + a, rb0);
        float o1 = fmaxf(fmaxf(ra1, rc1) + a, rb1);

        orow[0] = o0;
        if (has2) orow[1] = o1;
        orow += OW_;

        ra0 = rc0;   // slide window: row 2oh+2 becomes row 2(oh+1)
        ra1 = rc1;
    }
}

extern "C" void kernel_launch(void* const* d_in, const int* in_sizes, int n_in,
                              void* d_out, int out_size)
{
    // Identify inputs by element count (robust to metadata ordering):
    // f: 16*128*256*256 = 134217728, t: 128, ks/stride: scalars
    const float* f = nullptr;
    const float* t = nullptr;
    for (int i = 0; i < n_in; ++i) {
        if (in_sizes[i] == B_ * C_ * H_ * W_) f = (const float*)d_in[i];
        else if (in_sizes[i] == C_)           t = (const float*)d_in[i];
    }
    float* out = (float*)d_out;

    dim3 grid(B_ * C_, SEGS);
    parabolic_pool_kernel<<<grid, 64>>>(f, t, out);
}

// round 5
// speedup vs baseline: 1.0373x; 1.0373x over previous
#include <cuda_runtime.h>
#include <cstdint>

// ParabolicPool2D: out[b,c,oh,ow] = max_{p,q in 0..2} f[b,c,2*oh+p,2*ow+q] + h[c,p,q]
// h[c,p,q] = a[p] + a[q]  with a[0]=a[2]=-t[c]/2, a[1]=0   (separable)
//
//   rowred[r,ow] = max( max(f[r,2ow], f[r,2ow+2]) + a, f[r,2ow+1] )
//   out[oh,ow]   = max( max(rowred[2oh], rowred[2oh+2]) + a, rowred[2oh+1] )
//
// Each thread owns 2 output columns (one float4 + one scalar input load per row).
// Vertical register sliding window: 2 new input rows per output row.
// R4->R5: software-pipelined — prefetch next iteration's two rows before
// computing the current one, unroll 4, to deepen the outstanding-LDG queue.

#define B_  16
#define C_  128
#define H_  256
#define W_  256
#define OH_ 127
#define OW_ 127
#define SEGS 4
#define SEG_ROWS 32   // oh rows per segment (last segment has 31)

__global__ __launch_bounds__(64, 16)
void parabolic_pool_kernel(const float* __restrict__ f,
                           const float* __restrict__ t,
                           float* __restrict__ out)
{
    const int tx    = threadIdx.x;        // 0..63, owns output cols 2*tx, 2*tx+1
    const int plane = blockIdx.x;         // b*C + c
    const int seg   = blockIdx.y;         // oh segment

    const int c = plane & (C_ - 1);
    const float a = -0.5f * __ldg(&t[c]);

    const float* fp = f + (size_t)plane * (H_ * W_);
    float*       op = out + (size_t)plane * (OH_ * OW_);

    const int col  = tx * 4;              // 16B-aligned input column base
    const bool has2 = (tx < 63);          // second output column valid

    const int oh0 = seg * SEG_ROWS;
    const int nh  = min(SEG_ROWS, OH_ - oh0);

    // ---- prime: row-reduce input row 2*oh0 ----
    const float* row = fp + (2 * oh0) * W_ + col;
    float4 v  = *reinterpret_cast<const float4*>(row);
    float  v4 = has2 ? row[4] : 0.0f;

    float ra0 = fmaxf(fmaxf(v.x, v.z) + a, v.y);
    float ra1 = fmaxf(fmaxf(v.z, v4)  + a, v.w);

    // ---- prefetch rows for iteration 0 ----
    const float* rb = row + W_;
    const float* rc = row + 2 * W_;
    float4 vb  = *reinterpret_cast<const float4*>(rb);
    float4 vc  = *reinterpret_cast<const float4*>(rc);
    float  vb4 = has2 ? rb[4] : 0.0f;
    float  vc4 = has2 ? rc[4] : 0.0f;

    float* orow = op + oh0 * OW_ + 2 * tx;

    #pragma unroll 4
    for (int i = 0; i < nh; ++i) {
        // ---- prefetch rows for iteration i+1 (pointer-clamped on last iter:
        // loads stay unconditional/uniform; values are dead past the end) ----
        const bool more = (i + 1 < nh);
        const float* nrb = more ? (rc + W_)     : rc;
        const float* nrc = more ? (rc + 2 * W_) : rc;
        float4 nb  = *reinterpret_cast<const float4*>(nrb);
        float4 nc  = *reinterpret_cast<const float4*>(nrc);
        float  nb4 = has2 ? nrb[4] : 0.0f;
        float  nc4 = has2 ? nrc[4] : 0.0f;

        // ---- compute with current pair ----
        float rb0 = fmaxf(fmaxf(vb.x, vb.z) + a, vb.y);
        float rb1 = fmaxf(fmaxf(vb.z, vb4)  + a, vb.w);
        float rc0 = fmaxf(fmaxf(vc.x, vc.z) + a, vc.y);
        float rc1 = fmaxf(fmaxf(vc.z, vc4)  + a, vc.w);

        float o0 = fmaxf(fmaxf(ra0, rc0) + a, rb0);
        float o1 = fmaxf(fmaxf(ra1, rc1) + a, rb1);

        orow[0] = o0;
        if (has2) orow[1] = o1;
        orow += OW_;

        // ---- slide window ----
        ra0 = rc0;
        ra1 = rc1;
        vb = nb;  vc = nc;  vb4 = nb4;  vc4 = nc4;
        rc = nrc;
    }
}

extern "C" void kernel_launch(void* const* d_in, const int* in_sizes, int n_in,
                              void* d_out, int out_size)
{
    // Identify inputs by element count (robust to metadata ordering):
    // f: 16*128*256*256 = 134217728, t: 128
    const float* f = nullptr;
    const float* t = nullptr;
    for (int i = 0; i < n_in; ++i) {
        if (in_sizes[i] == B_ * C_ * H_ * W_) f = (const float*)d_in[i];
        else if (in_sizes[i] == C_)           t = (const float*)d_in[i];
    }
    float* out = (float*)d_out;

    dim3 grid(B_ * C_, SEGS);
    parabolic_pool_kernel<<<grid, 64>>>(f, t, out);
}